// round 12
// baseline (speedup 1.0000x reference)
#include <cuda_runtime.h>
#include <cuda_bf16.h>
#include <math.h>
#include <stdint.h>

#define BSZ   16384
#define DIM   512
#define KNUM  8192
#define NEG_SLOPE 0.01f

// ---- scratch (static device globals) ----
__device__ float g_esq[KNUM];
__device__ float g_H[(size_t)BSZ * DIM];            // fp32 hidden (exact, for refine)
__device__ __nv_bfloat16 g_Hb[(size_t)BSZ * DIM];   // bf16 hidden (GEMM input)
__device__ __nv_bfloat16 g_Eb[(size_t)KNUM * DIM];  // bf16 embeddings
__device__ __nv_bfloat16 g_W2b[(size_t)KNUM * DIM]; // bf16 W2
__device__ __nv_bfloat16 g_Xmb[(size_t)BSZ * DIM];  // bf16 mel input
__device__ __nv_bfloat16 g_Xeh[(size_t)BSZ * DIM];  // eeg hi/lo split
__device__ __nv_bfloat16 g_Xel[(size_t)BSZ * DIM];
__device__ __nv_bfloat16 g_W1h[(size_t)DIM * DIM];  // W1 hi/lo split
__device__ __nv_bfloat16 g_W1l[(size_t)DIM * DIM];
__device__ int   g_meli1[BSZ], g_meli2[BSZ];
__device__ int   g_logi1[BSZ], g_logi2[BSZ];
__device__ float g_lse[BSZ];
__device__ float g_loss[BSZ], g_match[BSZ];

// ============================================================
// common PTX helpers
// ============================================================
__device__ __forceinline__ uint32_t smem_u32(const void* p) {
    uint32_t a;
    asm("{ .reg .u64 t; cvta.to.shared.u64 t, %1; cvt.u32.u64 %0, t; }" : "=r"(a) : "l"(p));
    return a;
}
__device__ __forceinline__ void ldsm4(uint32_t& r0, uint32_t& r1, uint32_t& r2, uint32_t& r3,
                                      uint32_t addr) {
    asm volatile("ldmatrix.sync.aligned.m8n8.x4.shared.b16 {%0,%1,%2,%3}, [%4];"
                 : "=r"(r0), "=r"(r1), "=r"(r2), "=r"(r3) : "r"(addr));
}
__device__ __forceinline__ void cp16(void* dst, const void* src) {
    unsigned d = smem_u32(dst);
    asm volatile("cp.async.cg.shared.global [%0], [%1], 16;" :: "r"(d), "l"(src));
}
#define CP_COMMIT() asm volatile("cp.async.commit_group;" ::: "memory")

// bf16 m16n8k16
__device__ __forceinline__ void mma_bf16(float* d, const uint32_t* a, const uint32_t* b) {
    asm volatile(
        "mma.sync.aligned.m16n8k16.row.col.f32.bf16.bf16.f32 "
        "{%0,%1,%2,%3},{%4,%5,%6,%7},{%8,%9},{%0,%1,%2,%3};"
        : "+f"(d[0]), "+f"(d[1]), "+f"(d[2]), "+f"(d[3])
        : "r"(a[0]), "r"(a[1]), "r"(a[2]), "r"(a[3]), "r"(b[0]), "r"(b[1]));
}

// ============================================================
// big-GEMM (bf16), A-RESIDENT: CTA = 128 rows x all 8192 cols.
// A (128x512 bf16) loaded ONCE into smem (1040 B rows -> ldsm conflict-free);
// B streamed as 512 chunks (64 cols each) through a 3-stage ring.
// 8 warps (4x2), warp tile 32x64. 1 CTA/SM, grid 256 (128 mel + 128 logits).
// ============================================================
#define MROWS   128
#define NCOLS   128
#define BROWA   1040                       // A row: 512 bf16 = 1024 B + 16 pad
#define BROWB   144                        // B row: 64 bf16 = 128 B + 16 pad
#define A_BYTES (MROWS * BROWA)            // 133120
#define BSTAGE  (NCOLS * BROWB)            // 18432
#define SMEM_BIG (A_BYTES + 3 * BSTAGE)    // 188416

#define NCHUNK  512                        // 64 passes x 8 chunks

// load one B chunk (128 rows x 64 cols) for global chunk index g
__device__ __forceinline__ void ld_chunk_B(char* sbase, const __nv_bfloat16* B, int g, int tid)
{
    const int nt = g >> 3;
    const int kb = (g & 7) * 64;
    #pragma unroll
    for (int i = 0; i < 4; i++) {
        int f = tid + (i << 8);
        int r = f >> 3, c = f & 7;
        cp16(sbase + r * BROWB + c * 16,
             B + (size_t)(nt * NCOLS + r) * DIM + kb + c * 8);
    }
    CP_COMMIT();
}

// compute one chunk (4 k16 steps): A from resident smem, B from ring stage
__device__ __forceinline__ void compute_chunk(uint32_t aAddr, uint32_t bAddr, int kt,
                                              float acc[2][8][4])
{
    #pragma unroll
    for (int j = 0; j < 4; j++) {
        const uint32_t kbA = (uint32_t)(kt * 4 + j) * 32u;
        const uint32_t kbB = (uint32_t)j * 32u;
        uint32_t a[2][4], b[8][2];
        #pragma unroll
        for (int mi = 0; mi < 2; mi++)
            ldsm4(a[mi][0], a[mi][1], a[mi][2], a[mi][3],
                  aAddr + (uint32_t)mi * (16 * BROWA) + kbA);
        #pragma unroll
        for (int p = 0; p < 4; p++)
            ldsm4(b[2 * p][0], b[2 * p][1], b[2 * p + 1][0], b[2 * p + 1][1],
                  bAddr + (uint32_t)p * (16 * BROWB) + kbB);
        #pragma unroll
        for (int mi = 0; mi < 2; mi++)
            #pragma unroll
            for (int ni = 0; ni < 8; ni++)
                mma_bf16(acc[mi][ni], a[mi], b[ni]);
    }
}

// top-2 insertion with index tiebreak + dedupe
__device__ __forceinline__ void ins_min(float v, int i, float& v1, int& i1, float& v2, int& i2) {
    if (v < v1 || (v == v1 && i < i1)) {
        if (i != i1) { v2 = v1; i2 = i1; }
        v1 = v; i1 = i;
    } else if (i != i1 && (v < v2 || (v == v2 && i < i2))) { v2 = v; i2 = i; }
}
__device__ __forceinline__ void ins_max(float v, int i, float& v1, int& i1, float& v2, int& i2) {
    if (v > v1 || (v == v1 && i < i1)) {
        if (i != i1) { v2 = v1; i2 = i1; }
        v1 = v; i1 = i;
    } else if (i != i1 && (v > v2 || (v == v2 && i < i2))) { v2 = v; i2 = i; }
}

__global__ void __launch_bounds__(256, 1)
big_mma_all(const __nv_bfloat16* __restrict__ Amel,
            const __nv_bfloat16* __restrict__ Bmel,
            const __nv_bfloat16* __restrict__ Blog,
            const float* __restrict__ b2)
{
    extern __shared__ float smf[];
    char* sm = (char*)smf;
    char* sB = sm + A_BYTES;
    const int tid = threadIdx.x, w = tid >> 5, lane = tid & 31;
    const int wm = w >> 1, wn = w & 1, lr = lane >> 2, lq = lane & 3;
    const bool LOGITS = (blockIdx.x >= 128);
    const int row0 = (blockIdx.x & 127) * MROWS;
    const __nv_bfloat16* A = LOGITS ? (const __nv_bfloat16*)g_Hb : Amel;
    const __nv_bfloat16* B = LOGITS ? Blog : Bmel;
    const __nv_bfloat16* Ag = A + (size_t)row0 * DIM;

    // ---- load A resident (128x512 bf16, 1040B rows), 32 cp16/thread ----
    #pragma unroll
    for (int i = 0; i < 32; i++) {
        int f = tid + (i << 8);         // 0..8191
        int r = f >> 6, c = f & 63;     // row 0..127, 16B unit 0..63
        cp16(sm + r * BROWA + c * 16, Ag + (size_t)r * DIM + c * 8);
    }
    CP_COMMIT();
    ld_chunk_B(sB + 0 * BSTAGE, B, 0, tid);
    ld_chunk_B(sB + 1 * BSTAGE, B, 1, tid);

    const uint32_t aAddr = smem_u32(sm)
        + (uint32_t)((wm * 32 + (lane & 7) + ((lane >> 3) & 1) * 8) * BROWA
                     + ((lane >> 4) & 1) * 16);
    const uint32_t bBase = smem_u32(sB)
        + (uint32_t)((wn * 64 + (lane & 7) + ((lane >> 4) & 1) * 8) * BROWB
                     + ((lane >> 3) & 1) * 16);

    float v1[4], v2[4], s[4]; int i1[4], i2[4];
    #pragma unroll
    for (int st = 0; st < 4; st++) {
        v1[st] = LOGITS ? -INFINITY : INFINITY; v2[st] = v1[st];
        i1[st] = 0x7fffffff; i2[st] = 0x7fffffff;
        s[st] = 0.f;
    }

    float acc[2][8][4];
    for (int g = 0; g < NCHUNK; g++) {
        const int kt = g & 7;
        if (kt == 0) {
            #pragma unroll
            for (int mi = 0; mi < 2; mi++)
                #pragma unroll
                for (int ni = 0; ni < 8; ni++)
                    #pragma unroll
                    for (int j = 0; j < 4; j++) acc[mi][ni][j] = 0.f;
        }
        if (g < NCHUNK - 2) asm volatile("cp.async.wait_group 1;" ::: "memory");
        else                asm volatile("cp.async.wait_group 0;" ::: "memory");
        __syncthreads();
        compute_chunk(aAddr, bBase + (uint32_t)((g % 3) * BSTAGE), kt, acc);
        if (g + 2 < NCHUNK)
            ld_chunk_B(sB + ((g + 2) % 3) * BSTAGE, B, g + 2, tid);

        if (kt == 7) {
            const int nt = g >> 3;
            #pragma unroll
            for (int mi = 0; mi < 2; mi++)
                #pragma unroll
                for (int h = 0; h < 2; h++) {
                    const int st = mi * 2 + h;
                    if (LOGITS) {
                        float ssum = 0.f;
                        #pragma unroll
                        for (int ni = 0; ni < 8; ni++)
                            #pragma unroll
                            for (int cc = 0; cc < 2; cc++) {
                                int col = nt * NCOLS + wn * 64 + ni * 8 + lq * 2 + cc;
                                float x = acc[mi][ni][h * 2 + cc] + __ldg(&b2[col]);
                                ssum += __expf(x);   // logits bounded (~|x|<2): no overflow
                                if (x > v1[st]) { v2[st] = v1[st]; i2[st] = i1[st]; v1[st] = x; i1[st] = col; }
                                else if (x > v2[st]) { v2[st] = x; i2[st] = col; }
                            }
                        s[st] += ssum;
                    } else {
                        #pragma unroll
                        for (int ni = 0; ni < 8; ni++)
                            #pragma unroll
                            for (int cc = 0; cc < 2; cc++) {
                                int col = nt * NCOLS + wn * 64 + ni * 8 + lq * 2 + cc;
                                float d = fmaf(-2.f, acc[mi][ni][h * 2 + cc], __ldg(&g_esq[col]));
                                if (d < v1[st]) { v2[st] = v1[st]; i2[st] = i1[st]; v1[st] = d; i1[st] = col; }
                                else if (d < v2[st]) { v2[st] = d; i2[st] = col; }
                            }
                    }
                }
        }
    }

    // merge: 8 slots per row (wn x lq), rows 0..127 (reuses A region)
    __syncthreads();
    float* v1s = smf;                  float* v2s = smf + 1024;
    int*   i1s = (int*)(smf + 2048);   int*   i2s = (int*)(smf + 3072);
    float* ss  = smf + 4096;
    const int slot = wn * 4 + lq;
    #pragma unroll
    for (int mi = 0; mi < 2; mi++)
        #pragma unroll
        for (int h = 0; h < 2; h++) {
            int r  = wm * 32 + mi * 16 + lr + h * 8;
            int st = mi * 2 + h;
            v1s[r * 8 + slot] = v1[st]; v2s[r * 8 + slot] = v2[st];
            i1s[r * 8 + slot] = i1[st]; i2s[r * 8 + slot] = i2[st];
            if (LOGITS) ss[r * 8 + slot] = s[st];
        }
    __syncthreads();
    if (tid < 128) {
        const int grow = row0 + tid;
        if (LOGITS) {
            float bv1 = -INFINITY, bv2 = -INFINITY; int bi1 = 0x7fffffff, bi2 = 0x7fffffff;
            float S = 0.f;
            #pragma unroll
            for (int k = 0; k < 8; k++) {
                ins_max(v1s[tid * 8 + k], i1s[tid * 8 + k], bv1, bi1, bv2, bi2);
                ins_max(v2s[tid * 8 + k], i2s[tid * 8 + k], bv1, bi1, bv2, bi2);
                S += ss[tid * 8 + k];
            }
            g_logi1[grow] = bi1; g_logi2[grow] = bi2;
            g_lse[grow]   = logf(S);
        } else {
            float bv1 = INFINITY, bv2 = INFINITY; int bi1 = 0x7fffffff, bi2 = 0x7fffffff;
            #pragma unroll
            for (int k = 0; k < 8; k++) {
                ins_min(v1s[tid * 8 + k], i1s[tid * 8 + k], bv1, bi1, bv2, bi2);
                ins_min(v2s[tid * 8 + k], i2s[tid * 8 + k], bv1, bi1, bv2, bi2);
            }
            g_meli1[grow] = bi1; g_meli2[grow] = bi2;
        }
    }
}

// ============================================================
// cast kernels
// ============================================================
__global__ void conv_bf16(const float4* __restrict__ in, uint2* __restrict__ out, int n4) {
    int i = blockIdx.x * blockDim.x + threadIdx.x;
    if (i < n4) {
        float4 v = in[i];
        __nv_bfloat162 a = __floats2bfloat162_rn(v.x, v.y);
        __nv_bfloat162 b = __floats2bfloat162_rn(v.z, v.w);
        uint2 u; u.x = *(uint32_t*)&a; u.y = *(uint32_t*)&b;
        out[i] = u;
    }
}

// hi = bf16(x); lo = bf16(x - hi)
__global__ void conv_split(const float4* __restrict__ in,
                           uint2* __restrict__ hi, uint2* __restrict__ lo, int n4) {
    int i = blockIdx.x * blockDim.x + threadIdx.x;
    if (i < n4) {
        float4 v = in[i];
        __nv_bfloat16 hx = __float2bfloat16_rn(v.x), hy = __float2bfloat16_rn(v.y);
        __nv_bfloat16 hz = __float2bfloat16_rn(v.z), hw = __float2bfloat16_rn(v.w);
        __nv_bfloat162 ha; ha.x = hx; ha.y = hy;
        __nv_bfloat162 hb; hb.x = hz; hb.y = hw;
        __nv_bfloat162 la = __floats2bfloat162_rn(v.x - __bfloat162float(hx), v.y - __bfloat162float(hy));
        __nv_bfloat162 lb = __floats2bfloat162_rn(v.z - __bfloat162float(hz), v.w - __bfloat162float(hw));
        uint2 uh; uh.x = *(uint32_t*)&ha; uh.y = *(uint32_t*)&hb;
        uint2 ul; ul.x = *(uint32_t*)&la; ul.y = *(uint32_t*)&lb;
        hi[i] = uh; lo[i] = ul;
    }
}

// ============================================================
// h kernel: H = leakyrelu(X*W1^T + b1) via 3x bf16-split
// (Ah*Bh + Ah*Bl + Al*Bh, fp32 accum). CTA 128x256, k-chunk 64, 2-stage ring.
// ============================================================
#define H_AL   (128 * BROWB)
#define H_BH   (2 * 128 * BROWB)
#define H_BL   (H_BH + 256 * BROWB)
#define HSTAGE (H_BL + 256 * BROWB)     // 110592
#define SMEM_H (2 * HSTAGE)             // 221184

__device__ __forceinline__ void ld_chunk_h(char* sbase, int kb, int tid,
                                           const __nv_bfloat16* Ah, const __nv_bfloat16* Al,
                                           const __nv_bfloat16* Bh, const __nv_bfloat16* Bl)
{
    #pragma unroll
    for (int i = 0; i < 4; i++) {
        int f = tid + (i << 8);
        int r = f >> 3, c = f & 7;
        cp16(sbase +        r * BROWB + c * 16, Ah + (size_t)r * DIM + kb + c * 8);
        cp16(sbase + H_AL + r * BROWB + c * 16, Al + (size_t)r * DIM + kb + c * 8);
    }
    #pragma unroll
    for (int i = 0; i < 8; i++) {
        int f = tid + (i << 8);
        int r = f >> 3, c = f & 7;
        cp16(sbase + H_BH + r * BROWB + c * 16, Bh + (size_t)r * DIM + kb + c * 8);
        cp16(sbase + H_BL + r * BROWB + c * 16, Bl + (size_t)r * DIM + kb + c * 8);
    }
    CP_COMMIT();
}

__device__ __forceinline__ void compute_stage_h(const char* sbuf, float acc[4][8][4],
                                                int wm, int wn, int lane)
{
    const uint32_t sb = smem_u32(sbuf);
    const uint32_t aoff = (uint32_t)((wm * 64 + (lane & 7) + ((lane >> 3) & 1) * 8) * BROWB
                                     + ((lane >> 4) & 1) * 16);
    const uint32_t boff = (uint32_t)((wn * 64 + (lane & 7) + ((lane >> 4) & 1) * 8) * BROWB
                                     + ((lane >> 3) & 1) * 16);
    const uint32_t aH = sb + aoff, aL = sb + H_AL + aoff;
    const uint32_t bH = sb + H_BH + boff, bL = sb + H_BL + boff;
    #pragma unroll
    for (int k16 = 0; k16 < 4; k16++) {
        const uint32_t kb = (uint32_t)k16 * 32u;
        uint32_t ah[4][4], al[4][4], bh[8][2], bl[8][2];
        #pragma unroll
        for (int mi = 0; mi < 4; mi++) {
            ldsm4(ah[mi][0], ah[mi][1], ah[mi][2], ah[mi][3], aH + (uint32_t)mi * (16 * BROWB) + kb);
            ldsm4(al[mi][0], al[mi][1], al[mi][2], al[mi][3], aL + (uint32_t)mi * (16 * BROWB) + kb);
        }
        #pragma unroll
        for (int p = 0; p < 4; p++) {
            ldsm4(bh[2*p][0], bh[2*p][1], bh[2*p+1][0], bh[2*p+1][1], bH + (uint32_t)p * (16 * BROWB) + kb);
            ldsm4(bl[2*p][0], bl[2*p][1], bl[2*p+1][0], bl[2*p+1][1], bL + (uint32_t)p * (16 * BROWB) + kb);
        }
        #pragma unroll
        for (int mi = 0; mi < 4; mi++)
            #pragma unroll
            for (int ni = 0; ni < 8; ni++) {
                mma_bf16(acc[mi][ni], ah[mi], bh[ni]);
                mma_bf16(acc[mi][ni], ah[mi], bl[ni]);
                mma_bf16(acc[mi][ni], al[mi], bh[ni]);
            }
    }
}

__global__ void __launch_bounds__(256, 1)
h_mma_kernel(const float* __restrict__ b1)
{
    extern __shared__ float smf[];
    char* sm = (char*)smf;
    const int tid = threadIdx.x, w = tid >> 5, lane = tid & 31;
    const int wm = w >> 2, wn = w & 3, lr = lane >> 2, lq = lane & 3;
    const int row0 = blockIdx.x * 128;
    const int col0 = blockIdx.y * 256;
    const __nv_bfloat16* Ah = g_Xeh + (size_t)row0 * DIM;
    const __nv_bfloat16* Al = g_Xel + (size_t)row0 * DIM;
    const __nv_bfloat16* Bh = g_W1h + (size_t)col0 * DIM;
    const __nv_bfloat16* Bl = g_W1l + (size_t)col0 * DIM;

    float acc[4][8][4];
    #pragma unroll
    for (int mi = 0; mi < 4; mi++)
        #pragma unroll
        for (int ni = 0; ni < 8; ni++)
            #pragma unroll
            for (int j = 0; j < 4; j++) acc[mi][ni][j] = 0.f;

    ld_chunk_h(sm + 0 * HSTAGE, 0,  tid, Ah, Al, Bh, Bl);
    ld_chunk_h(sm + 1 * HSTAGE, 64, tid, Ah, Al, Bh, Bl);

    for (int kt = 0; kt < 8; kt++) {
        if (kt < 7) asm volatile("cp.async.wait_group 1;" ::: "memory");
        else        asm volatile("cp.async.wait_group 0;" ::: "memory");
        __syncthreads();
        compute_stage_h(sm + (kt & 1) * HSTAGE, acc, wm, wn, lane);
        if (kt + 2 < 8) {
            __syncthreads();
            ld_chunk_h(sm + (kt & 1) * HSTAGE, (kt + 2) * 64, tid, Ah, Al, Bh, Bl);
        }
    }

    #pragma unroll
    for (int mi = 0; mi < 4; mi++)
        #pragma unroll
        for (int h = 0; h < 2; h++) {
            int r = row0 + wm * 64 + mi * 16 + lr + h * 8;
            #pragma unroll
            for (int ni = 0; ni < 8; ni++) {
                int c = col0 + wn * 64 + ni * 8 + lq * 2;
                float x0 = acc[mi][ni][h * 2 + 0] + __ldg(&b1[c + 0]);
                float x1 = acc[mi][ni][h * 2 + 1] + __ldg(&b1[c + 1]);
                x0 = (x0 >= 0.f) ? x0 : NEG_SLOPE * x0;
                x1 = (x1 >= 0.f) ? x1 : NEG_SLOPE * x1;
                *(float2*)(g_H + (size_t)r * DIM + c) = make_float2(x0, x1);
                __nv_bfloat162 hb = __floats2bfloat162_rn(x0, x1);
                *(uint32_t*)(g_Hb + (size_t)r * DIM + c) = *(uint32_t*)&hb;
            }
        }
}

// ============================================================
// ||e_k||^2
// ============================================================
__global__ void esq_kernel(const float* __restrict__ E) {
    int row  = blockIdx.x * (blockDim.x >> 5) + (threadIdx.x >> 5);
    int lane = threadIdx.x & 31;
    const float* e = E + (size_t)row * DIM;
    float s = 0.f;
    for (int c = lane; c < DIM; c += 32) { float v = e[c]; s = fmaf(v, v, s); }
    #pragma unroll
    for (int o = 16; o; o >>= 1) s += __shfl_xor_sync(0xffffffffu, s, o);
    if (lane == 0) g_esq[row] = s;
}

// ============================================================
// fp32 refine: exact re-evaluation of top-2 candidates per row
// ============================================================
__device__ __forceinline__ float dot512(const float* __restrict__ a,
                                        const float* __restrict__ b, int lane)
{
    float s = 0.f;
    #pragma unroll
    for (int t = 0; t < 4; t++) {
        float4 x = *(const float4*)(a + (lane + 32 * t) * 4);
        float4 y = *(const float4*)(b + (lane + 32 * t) * 4);
        s = fmaf(x.x, y.x, s); s = fmaf(x.y, y.y, s);
        s = fmaf(x.z, y.z, s); s = fmaf(x.w, y.w, s);
    }
    #pragma unroll
    for (int o = 16; o; o >>= 1) s += __shfl_xor_sync(0xffffffffu, s, o);
    return s;
}

__global__ void __launch_bounds__(256)
refine_kernel(const float* __restrict__ Xmel, const float* __restrict__ E,
              const float* __restrict__ W2,  const float* __restrict__ b2)
{
    const int warp = threadIdx.x >> 5, lane = threadIdx.x & 31;
    const int row = blockIdx.x * 8 + warp;
    if (row >= BSZ) return;

    const float* xr = Xmel + (size_t)row * DIM;
    const float* hr = g_H  + (size_t)row * DIM;

    int mi1 = g_meli1[row], mi2 = g_meli2[row];
    float d1 = g_esq[mi1] - 2.f * dot512(xr, E + (size_t)mi1 * DIM, lane);
    float d2 = g_esq[mi2] - 2.f * dot512(xr, E + (size_t)mi2 * DIM, lane);
    int mel_idx = (d1 < d2 || (d1 == d2 && mi1 < mi2)) ? mi1 : mi2;

    int j1 = g_logi1[row], j2 = g_logi2[row];
    float l1 = dot512(hr, W2 + (size_t)j1 * DIM, lane) + b2[j1];
    float l2 = dot512(hr, W2 + (size_t)j2 * DIM, lane) + b2[j2];
    int eeg_idx = (l1 > l2 || (l1 == l2 && j1 < j2)) ? j1 : j2;

    float t = dot512(hr, W2 + (size_t)mel_idx * DIM, lane) + b2[mel_idx];

    if (lane == 0) {
        g_loss[row]  = g_lse[row] - t;
        g_match[row] = (eeg_idx == mel_idx) ? 1.f : 0.f;
    }
}

// ============================================================
// final mean reduction
// ============================================================
__global__ void reduce_kernel(float* __restrict__ out) {
    __shared__ float sl[1024];
    __shared__ float sa[1024];
    int tid = threadIdx.x;
    float a = 0.f, b = 0.f;
    for (int i = tid; i < BSZ; i += 1024) { a += g_loss[i]; b += g_match[i]; }
    sl[tid] = a; sa[tid] = b;
    __syncthreads();
    for (int o = 512; o; o >>= 1) {
        if (tid < o) { sl[tid] += sl[tid + o]; sa[tid] += sa[tid + o]; }
        __syncthreads();
    }
    if (tid == 0) {
        out[0] = sl[0] / (float)BSZ;
        out[1] = sa[0] / (float)BSZ;
    }
}

// ============================================================
extern "C" void kernel_launch(void* const* d_in, const int* in_sizes, int n_in,
                              void* d_out, int out_size)
{
    (void)in_sizes; (void)n_in; (void)out_size;
    const float* eeg = (const float*)d_in[0];
    const float* mel = (const float*)d_in[1];
    const float* emb = (const float*)d_in[2];
    const float* W1  = (const float*)d_in[3];
    const float* b1  = (const float*)d_in[4];
    const float* W2  = (const float*)d_in[5];
    const float* b2  = (const float*)d_in[6];
    float* out = (float*)d_out;

    cudaFuncSetAttribute(big_mma_all,  cudaFuncAttributeMaxDynamicSharedMemorySize, SMEM_BIG);
    cudaFuncSetAttribute(h_mma_kernel, cudaFuncAttributeMaxDynamicSharedMemorySize, SMEM_H);

    __nv_bfloat16 *dEb, *dW2b, *dXmb, *dXeh, *dXel, *dW1h, *dW1l;
    cudaGetSymbolAddress((void**)&dEb,  g_Eb);
    cudaGetSymbolAddress((void**)&dW2b, g_W2b);
    cudaGetSymbolAddress((void**)&dXmb, g_Xmb);
    cudaGetSymbolAddress((void**)&dXeh, g_Xeh);
    cudaGetSymbolAddress((void**)&dXel, g_Xel);
    cudaGetSymbolAddress((void**)&dW1h, g_W1h);
    cudaGetSymbolAddress((void**)&dW1l, g_W1l);

    esq_kernel<<<KNUM / 8, 256>>>(emb);
    conv_bf16<<<(KNUM * DIM / 4 + 255) / 256, 256>>>((const float4*)emb, (uint2*)dEb,  KNUM * DIM / 4);
    conv_bf16<<<(KNUM * DIM / 4 + 255) / 256, 256>>>((const float4*)W2,  (uint2*)dW2b, KNUM * DIM / 4);
    conv_bf16<<<(BSZ * DIM / 4 + 255) / 256, 256>>>((const float4*)mel, (uint2*)dXmb, BSZ * DIM / 4);
    conv_split<<<(BSZ * DIM / 4 + 255) / 256, 256>>>((const float4*)eeg, (uint2*)dXeh, (uint2*)dXel, BSZ * DIM / 4);
    conv_split<<<(DIM * DIM / 4 + 255) / 256, 256>>>((const float4*)W1, (uint2*)dW1h, (uint2*)dW1l, DIM * DIM / 4);
    h_mma_kernel<<<dim3(BSZ / 128, DIM / 256), 256, SMEM_H>>>(b1);
    big_mma_all<<<256, 256, SMEM_BIG>>>(dXmb, dEb, dW2b, b2);
    refine_kernel<<<BSZ / 8, 256>>>(mel, emb, W2, b2);
    reduce_kernel<<<1, 1024>>>(out);
}

// round 14
// speedup vs baseline: 1.1667x; 1.1667x over previous
#include <cuda_runtime.h>
#include <cuda_bf16.h>
#include <math.h>
#include <stdint.h>

#define BSZ   16384
#define DIM   512
#define KNUM  8192
#define NEG_SLOPE 0.01f

// ---- scratch (static device globals) ----
__device__ float g_esq[KNUM];
__device__ float g_H[(size_t)BSZ * DIM];            // fp32 hidden (exact, for refine)
__device__ __nv_bfloat16 g_Hb[(size_t)BSZ * DIM];   // bf16 hidden (GEMM input)
__device__ __nv_bfloat16 g_Eb[(size_t)KNUM * DIM];  // bf16 embeddings
__device__ __nv_bfloat16 g_W2b[(size_t)KNUM * DIM]; // bf16 W2
__device__ __nv_bfloat16 g_Xmb[(size_t)BSZ * DIM];  // bf16 mel input
__device__ __nv_bfloat16 g_Xeh[(size_t)BSZ * DIM];  // eeg hi/lo split
__device__ __nv_bfloat16 g_Xel[(size_t)BSZ * DIM];
__device__ __nv_bfloat16 g_W1h[(size_t)DIM * DIM];  // W1 hi/lo split
__device__ __nv_bfloat16 g_W1l[(size_t)DIM * DIM];
__device__ int   g_meli1[BSZ], g_meli2[BSZ];
__device__ int   g_logi1[BSZ], g_logi2[BSZ];
__device__ float g_lse[BSZ];
__device__ float g_loss[BSZ], g_match[BSZ];

// ============================================================
// common PTX helpers
// ============================================================
__device__ __forceinline__ uint32_t smem_u32(const void* p) {
    uint32_t a;
    asm("{ .reg .u64 t; cvta.to.shared.u64 t, %1; cvt.u32.u64 %0, t; }" : "=r"(a) : "l"(p));
    return a;
}
__device__ __forceinline__ void ldsm4(uint32_t& r0, uint32_t& r1, uint32_t& r2, uint32_t& r3,
                                      uint32_t addr) {
    asm volatile("ldmatrix.sync.aligned.m8n8.x4.shared.b16 {%0,%1,%2,%3}, [%4];"
                 : "=r"(r0), "=r"(r1), "=r"(r2), "=r"(r3) : "r"(addr));
}
__device__ __forceinline__ void cp16(void* dst, const void* src) {
    unsigned d = smem_u32(dst);
    asm volatile("cp.async.cg.shared.global [%0], [%1], 16;" :: "r"(d), "l"(src));
}
#define CP_COMMIT() asm volatile("cp.async.commit_group;" ::: "memory")

// bf16 m16n8k16
__device__ __forceinline__ void mma_bf16(float* d, const uint32_t* a, const uint32_t* b) {
    asm volatile(
        "mma.sync.aligned.m16n8k16.row.col.f32.bf16.bf16.f32 "
        "{%0,%1,%2,%3},{%4,%5,%6,%7},{%8,%9},{%0,%1,%2,%3};"
        : "+f"(d[0]), "+f"(d[1]), "+f"(d[2]), "+f"(d[3])
        : "r"(a[0]), "r"(a[1]), "r"(a[2]), "r"(a[3]), "r"(b[0]), "r"(b[1]));
}

// ============================================================
// big-GEMM (bf16): CTA tile 128(M) x 128(N-pass), k-chunk 64, 8 warps (4x2),
// warp tile 32x64, 3-stage cp.async ring. 2 CTAs/SM (occupancy-driven overlap).
// smem row = 144 B (128 B data + 16 pad) -> conflict-free ldmatrix.
// ============================================================
#define MROWS   128
#define NCOLS   128
#define BROWB   144
#define BSTAGE  ((MROWS + NCOLS) * BROWB)   // 36864 B
#define SMEM_BIG (3 * BSTAGE)               // 110592 B -> 2 CTAs/SM

// chunk loader: A[128][64] + B[128][64] bf16 -> one stage (256 threads, 8 cp16 each)
__device__ __forceinline__ void ld_chunk_bf(char* sbase,
                                            const __nv_bfloat16* Ag,
                                            const __nv_bfloat16* Bg,
                                            int kb, int tid)
{
    #pragma unroll
    for (int i = 0; i < 4; i++) {
        int f = tid + (i << 8);           // 0..1023
        int r = f >> 3, c = f & 7;        // A row 0..127
        cp16(sbase + r * BROWB + c * 16, Ag + (size_t)r * DIM + kb + c * 8);
    }
    #pragma unroll
    for (int i = 0; i < 4; i++) {
        int f = tid + (i << 8);
        int r = f >> 3, c = f & 7;        // B row 0..127
        cp16(sbase + (128 + r) * BROWB + c * 16, Bg + (size_t)r * DIM + kb + c * 8);
    }
    CP_COMMIT();
}

// 8-warp compute (4x2): warp tile 32x64, acc[2][8][4]
__device__ __forceinline__ void compute_stage_bf(const char* sbuf, float acc[2][8][4],
                                                 int wm, int wn, int lane)
{
    const uint32_t sb = smem_u32(sbuf);
    const uint32_t aAddr = sb + (uint32_t)((wm * 32 + (lane & 7) + ((lane >> 3) & 1) * 8) * BROWB
                                           + ((lane >> 4) & 1) * 16);
    const uint32_t bAddr = sb + (uint32_t)((128 + wn * 64 + (lane & 7) + ((lane >> 4) & 1) * 8) * BROWB
                                           + ((lane >> 3) & 1) * 16);
    #pragma unroll
    for (int k16 = 0; k16 < 4; k16++) {
        const uint32_t kb = (uint32_t)k16 * 32u;
        uint32_t a[2][4], b[8][2];
        #pragma unroll
        for (int mi = 0; mi < 2; mi++)
            ldsm4(a[mi][0], a[mi][1], a[mi][2], a[mi][3],
                  aAddr + (uint32_t)mi * (16 * BROWB) + kb);
        #pragma unroll
        for (int p = 0; p < 4; p++)
            ldsm4(b[2 * p][0], b[2 * p][1], b[2 * p + 1][0], b[2 * p + 1][1],
                  bAddr + (uint32_t)p * (16 * BROWB) + kb);
        #pragma unroll
        for (int mi = 0; mi < 2; mi++)
            #pragma unroll
            for (int ni = 0; ni < 8; ni++)
                mma_bf16(acc[mi][ni], a[mi], b[ni]);
    }
}

__device__ __forceinline__ void gemm_k512_bf(const __nv_bfloat16* Ag, const __nv_bfloat16* Bg,
                                             char* sm, float acc[2][8][4],
                                             int tid, int wm, int wn, int lane)
{
    #pragma unroll
    for (int mi = 0; mi < 2; mi++)
        #pragma unroll
        for (int ni = 0; ni < 8; ni++)
            #pragma unroll
            for (int j = 0; j < 4; j++) acc[mi][ni][j] = 0.f;

    __syncthreads();
    ld_chunk_bf(sm + 0 * BSTAGE, Ag, Bg, 0,  tid);
    ld_chunk_bf(sm + 1 * BSTAGE, Ag, Bg, 64, tid);

    for (int kt = 0; kt < 8; kt++) {
        if (kt < 7) asm volatile("cp.async.wait_group 1;" ::: "memory");
        else        asm volatile("cp.async.wait_group 0;" ::: "memory");
        __syncthreads();
        compute_stage_bf(sm + (kt % 3) * BSTAGE, acc, wm, wn, lane);
        if (kt + 2 < 8)
            ld_chunk_bf(sm + ((kt + 2) % 3) * BSTAGE, Ag, Bg, (kt + 2) * 64, tid);
    }
}

// top-2 insertion with index tiebreak + dedupe
__device__ __forceinline__ void ins_min(float v, int i, float& v1, int& i1, float& v2, int& i2) {
    if (v < v1 || (v == v1 && i < i1)) {
        if (i != i1) { v2 = v1; i2 = i1; }
        v1 = v; i1 = i;
    } else if (i != i1 && (v < v2 || (v == v2 && i < i2))) { v2 = v; i2 = i; }
}
__device__ __forceinline__ void ins_max(float v, int i, float& v1, int& i1, float& v2, int& i2) {
    if (v > v1 || (v == v1 && i < i1)) {
        if (i != i1) { v2 = v1; i2 = i1; }
        v1 = v; i1 = i;
    } else if (i != i1 && (v > v2 || (v == v2 && i < i2))) { v2 = v; i2 = i; }
}

// ============================================================
// MERGED big fused kernel: grid 256, 2 CTAs/SM.
// bx<128 -> mel argmin block bx; bx>=128 -> logits block bx-128 (reads g_Hb).
// Logits epilogue: max-free sum-exp (logits bounded |x|<~2 -> fp32-safe).
// ============================================================
__global__ void __launch_bounds__(256, 2)
big_mma_all(const __nv_bfloat16* __restrict__ Amel,
            const __nv_bfloat16* __restrict__ Bmel,
            const __nv_bfloat16* __restrict__ Blog,
            const float* __restrict__ b2)
{
    extern __shared__ float smf[];
    char* sm = (char*)smf;
    const int tid = threadIdx.x, w = tid >> 5, lane = tid & 31;
    const int wm = w >> 1, wn = w & 1, lr = lane >> 2, lq = lane & 3;
    const bool LOGITS = (blockIdx.x >= 128);
    const int row0 = (blockIdx.x & 127) * MROWS;
    const __nv_bfloat16* A = LOGITS ? (const __nv_bfloat16*)g_Hb : Amel;
    const __nv_bfloat16* B = LOGITS ? Blog : Bmel;
    const __nv_bfloat16* Ag = A + (size_t)row0 * DIM;

    float v1[4], v2[4], s[4]; int i1[4], i2[4];
    #pragma unroll
    for (int st = 0; st < 4; st++) {
        v1[st] = LOGITS ? -INFINITY : INFINITY; v2[st] = v1[st];
        i1[st] = 0x7fffffff; i2[st] = 0x7fffffff;
        s[st] = 0.f;
    }

    float acc[2][8][4];
    for (int nt = 0; nt < KNUM / NCOLS; nt++) {
        gemm_k512_bf(Ag, B + (size_t)nt * NCOLS * DIM, sm, acc, tid, wm, wn, lane);

        #pragma unroll
        for (int mi = 0; mi < 2; mi++)
            #pragma unroll
            for (int h = 0; h < 2; h++) {
                const int st = mi * 2 + h;
                if (LOGITS) {
                    float ssum = 0.f;
                    #pragma unroll
                    for (int ni = 0; ni < 8; ni++)
                        #pragma unroll
                        for (int cc = 0; cc < 2; cc++) {
                            int col = nt * NCOLS + wn * 64 + ni * 8 + lq * 2 + cc;
                            float x = acc[mi][ni][h * 2 + cc] + __ldg(&b2[col]);
                            ssum += __expf(x);   // bounded logits: no overflow risk
                            if (x > v1[st]) { v2[st] = v1[st]; i2[st] = i1[st]; v1[st] = x; i1[st] = col; }
                            else if (x > v2[st]) { v2[st] = x; i2[st] = col; }
                        }
                    s[st] += ssum;
                } else {
                    #pragma unroll
                    for (int ni = 0; ni < 8; ni++)
                        #pragma unroll
                        for (int cc = 0; cc < 2; cc++) {
                            int col = nt * NCOLS + wn * 64 + ni * 8 + lq * 2 + cc;
                            float d = fmaf(-2.f, acc[mi][ni][h * 2 + cc], __ldg(&g_esq[col]));
                            if (d < v1[st]) { v2[st] = v1[st]; i2[st] = i1[st]; v1[st] = d; i1[st] = col; }
                            else if (d < v2[st]) { v2[st] = d; i2[st] = col; }
                        }
                }
            }
    }

    // merge: 8 slots per row (wn x lq), rows 0..127
    __syncthreads();
    float* v1s = smf;                  float* v2s = smf + 1024;
    int*   i1s = (int*)(smf + 2048);   int*   i2s = (int*)(smf + 3072);
    float* ss  = smf + 4096;
    const int slot = wn * 4 + lq;
    #pragma unroll
    for (int mi = 0; mi < 2; mi++)
        #pragma unroll
        for (int h = 0; h < 2; h++) {
            int r  = wm * 32 + mi * 16 + lr + h * 8;
            int st = mi * 2 + h;
            v1s[r * 8 + slot] = v1[st]; v2s[r * 8 + slot] = v2[st];
            i1s[r * 8 + slot] = i1[st]; i2s[r * 8 + slot] = i2[st];
            if (LOGITS) ss[r * 8 + slot] = s[st];
        }
    __syncthreads();
    if (tid < 128) {
        const int grow = row0 + tid;
        if (LOGITS) {
            float bv1 = -INFINITY, bv2 = -INFINITY; int bi1 = 0x7fffffff, bi2 = 0x7fffffff;
            float S = 0.f;
            #pragma unroll
            for (int k = 0; k < 8; k++) {
                ins_max(v1s[tid * 8 + k], i1s[tid * 8 + k], bv1, bi1, bv2, bi2);
                ins_max(v2s[tid * 8 + k], i2s[tid * 8 + k], bv1, bi1, bv2, bi2);
                S += ss[tid * 8 + k];
            }
            g_logi1[grow] = bi1; g_logi2[grow] = bi2;
            g_lse[grow]   = logf(S);
        } else {
            float bv1 = INFINITY, bv2 = INFINITY; int bi1 = 0x7fffffff, bi2 = 0x7fffffff;
            #pragma unroll
            for (int k = 0; k < 8; k++) {
                ins_min(v1s[tid * 8 + k], i1s[tid * 8 + k], bv1, bi1, bv2, bi2);
                ins_min(v2s[tid * 8 + k], i2s[tid * 8 + k], bv1, bi1, bv2, bi2);
            }
            g_meli1[grow] = bi1; g_meli2[grow] = bi2;
        }
    }
}

// ============================================================
// fused cast kernel: emb->bf16, W2->bf16, mel->bf16, eeg->split, W1->split
// index space in float4 units, ranges concatenated.
// ============================================================
#define N4_EMB  (KNUM * DIM / 4)            // 1048576
#define N4_W2   (KNUM * DIM / 4)
#define N4_MEL  (BSZ * DIM / 4)             // 2097152
#define N4_EEG  (BSZ * DIM / 4)
#define N4_W1   (DIM * DIM / 4)             // 65536
#define N4_TOT  (N4_EMB + N4_W2 + N4_MEL + N4_EEG + N4_W1)

__device__ __forceinline__ uint2 pack_bf16(float4 v) {
    __nv_bfloat162 a = __floats2bfloat162_rn(v.x, v.y);
    __nv_bfloat162 b = __floats2bfloat162_rn(v.z, v.w);
    uint2 u; u.x = *(uint32_t*)&a; u.y = *(uint32_t*)&b;
    return u;
}

__global__ void conv_all(const float4* __restrict__ emb, const float4* __restrict__ W2,
                         const float4* __restrict__ mel, const float4* __restrict__ eeg,
                         const float4* __restrict__ W1,
                         uint2* __restrict__ oE, uint2* __restrict__ oW2,
                         uint2* __restrict__ oM,
                         uint2* __restrict__ oXh, uint2* __restrict__ oXl,
                         uint2* __restrict__ oWh, uint2* __restrict__ oWl)
{
    int i = blockIdx.x * blockDim.x + threadIdx.x;
    if (i >= N4_TOT) return;
    if (i < N4_EMB) {
        oE[i] = pack_bf16(emb[i]);
    } else if (i < N4_EMB + N4_W2) {
        int j = i - N4_EMB;
        oW2[j] = pack_bf16(W2[j]);
    } else if (i < N4_EMB + N4_W2 + N4_MEL) {
        int j = i - N4_EMB - N4_W2;
        oM[j] = pack_bf16(mel[j]);
    } else if (i < N4_EMB + N4_W2 + N4_MEL + N4_EEG) {
        int j = i - N4_EMB - N4_W2 - N4_MEL;
        float4 v = eeg[j];
        __nv_bfloat16 hx = __float2bfloat16_rn(v.x), hy = __float2bfloat16_rn(v.y);
        __nv_bfloat16 hz = __float2bfloat16_rn(v.z), hw = __float2bfloat16_rn(v.w);
        __nv_bfloat162 ha; ha.x = hx; ha.y = hy;
        __nv_bfloat162 hb; hb.x = hz; hb.y = hw;
        __nv_bfloat162 la = __floats2bfloat162_rn(v.x - __bfloat162float(hx), v.y - __bfloat162float(hy));
        __nv_bfloat162 lb = __floats2bfloat162_rn(v.z - __bfloat162float(hz), v.w - __bfloat162float(hw));
        uint2 uh; uh.x = *(uint32_t*)&ha; uh.y = *(uint32_t*)&hb;
        uint2 ul; ul.x = *(uint32_t*)&la; ul.y = *(uint32_t*)&lb;
        oXh[j] = uh; oXl[j] = ul;
    } else {
        int j = i - N4_EMB - N4_W2 - N4_MEL - N4_EEG;
        float4 v = W1[j];
        __nv_bfloat16 hx = __float2bfloat16_rn(v.x), hy = __float2bfloat16_rn(v.y);
        __nv_bfloat16 hz = __float2bfloat16_rn(v.z), hw = __float2bfloat16_rn(v.w);
        __nv_bfloat162 ha; ha.x = hx; ha.y = hy;
        __nv_bfloat162 hb; hb.x = hz; hb.y = hw;
        __nv_bfloat162 la = __floats2bfloat162_rn(v.x - __bfloat162float(hx), v.y - __bfloat162float(hy));
        __nv_bfloat162 lb = __floats2bfloat162_rn(v.z - __bfloat162float(hz), v.w - __bfloat162float(hw));
        uint2 uh; uh.x = *(uint32_t*)&ha; uh.y = *(uint32_t*)&hb;
        uint2 ul; ul.x = *(uint32_t*)&la; ul.y = *(uint32_t*)&lb;
        oWh[j] = uh; oWl[j] = ul;
    }
}

// ============================================================
// h kernel: H = leakyrelu(X*W1^T + b1) via 3x bf16-split
// (Ah*Bh + Ah*Bl + Al*Bh, fp32 accum). CTA 128x256, k-chunk 64, 2-stage ring.
// ============================================================
#define H_AL   (128 * BROWB)
#define H_BH   (2 * 128 * BROWB)
#define H_BL   (H_BH + 256 * BROWB)
#define HSTAGE (H_BL + 256 * BROWB)     // 110592
#define SMEM_H (2 * HSTAGE)             // 221184

__device__ __forceinline__ void ld_chunk_h(char* sbase, int kb, int tid,
                                           const __nv_bfloat16* Ah, const __nv_bfloat16* Al,
                                           const __nv_bfloat16* Bh, const __nv_bfloat16* Bl)
{
    #pragma unroll
    for (int i = 0; i < 4; i++) {
        int f = tid + (i << 8);
        int r = f >> 3, c = f & 7;
        cp16(sbase +        r * BROWB + c * 16, Ah + (size_t)r * DIM + kb + c * 8);
        cp16(sbase + H_AL + r * BROWB + c * 16, Al + (size_t)r * DIM + kb + c * 8);
    }
    #pragma unroll
    for (int i = 0; i < 8; i++) {
        int f = tid + (i << 8);
        int r = f >> 3, c = f & 7;
        cp16(sbase + H_BH + r * BROWB + c * 16, Bh + (size_t)r * DIM + kb + c * 8);
        cp16(sbase + H_BL + r * BROWB + c * 16, Bl + (size_t)r * DIM + kb + c * 8);
    }
    CP_COMMIT();
}

__device__ __forceinline__ void compute_stage_h(const char* sbuf, float acc[4][8][4],
                                                int wm, int wn, int lane)
{
    const uint32_t sb = smem_u32(sbuf);
    const uint32_t aoff = (uint32_t)((wm * 64 + (lane & 7) + ((lane >> 3) & 1) * 8) * BROWB
                                     + ((lane >> 4) & 1) * 16);
    const uint32_t boff = (uint32_t)((wn * 64 + (lane & 7) + ((lane >> 4) & 1) * 8) * BROWB
                                     + ((lane >> 3) & 1) * 16);
    const uint32_t aH = sb + aoff, aL = sb + H_AL + aoff;
    const uint32_t bH = sb + H_BH + boff, bL = sb + H_BL + boff;
    #pragma unroll
    for (int k16 = 0; k16 < 4; k16++) {
        const uint32_t kb = (uint32_t)k16 * 32u;
        uint32_t ah[4][4], al[4][4], bh[8][2], bl[8][2];
        #pragma unroll
        for (int mi = 0; mi < 4; mi++) {
            ldsm4(ah[mi][0], ah[mi][1], ah[mi][2], ah[mi][3], aH + (uint32_t)mi * (16 * BROWB) + kb);
            ldsm4(al[mi][0], al[mi][1], al[mi][2], al[mi][3], aL + (uint32_t)mi * (16 * BROWB) + kb);
        }
        #pragma unroll
        for (int p = 0; p < 4; p++) {
            ldsm4(bh[2*p][0], bh[2*p][1], bh[2*p+1][0], bh[2*p+1][1], bH + (uint32_t)p * (16 * BROWB) + kb);
            ldsm4(bl[2*p][0], bl[2*p][1], bl[2*p+1][0], bl[2*p+1][1], bL + (uint32_t)p * (16 * BROWB) + kb);
        }
        #pragma unroll
        for (int mi = 0; mi < 4; mi++)
            #pragma unroll
            for (int ni = 0; ni < 8; ni++) {
                mma_bf16(acc[mi][ni], ah[mi], bh[ni]);
                mma_bf16(acc[mi][ni], ah[mi], bl[ni]);
                mma_bf16(acc[mi][ni], al[mi], bh[ni]);
            }
    }
}

__global__ void __launch_bounds__(256, 1)
h_mma_kernel(const float* __restrict__ b1)
{
    extern __shared__ float smf[];
    char* sm = (char*)smf;
    const int tid = threadIdx.x, w = tid >> 5, lane = tid & 31;
    const int wm = w >> 2, wn = w & 3, lr = lane >> 2, lq = lane & 3;
    const int row0 = blockIdx.x * 128;
    const int col0 = blockIdx.y * 256;
    const __nv_bfloat16* Ah = g_Xeh + (size_t)row0 * DIM;
    const __nv_bfloat16* Al = g_Xel + (size_t)row0 * DIM;
    const __nv_bfloat16* Bh = g_W1h + (size_t)col0 * DIM;
    const __nv_bfloat16* Bl = g_W1l + (size_t)col0 * DIM;

    float acc[4][8][4];
    #pragma unroll
    for (int mi = 0; mi < 4; mi++)
        #pragma unroll
        for (int ni = 0; ni < 8; ni++)
            #pragma unroll
            for (int j = 0; j < 4; j++) acc[mi][ni][j] = 0.f;

    ld_chunk_h(sm + 0 * HSTAGE, 0,  tid, Ah, Al, Bh, Bl);
    ld_chunk_h(sm + 1 * HSTAGE, 64, tid, Ah, Al, Bh, Bl);

    for (int kt = 0; kt < 8; kt++) {
        if (kt < 7) asm volatile("cp.async.wait_group 1;" ::: "memory");
        else        asm volatile("cp.async.wait_group 0;" ::: "memory");
        __syncthreads();
        compute_stage_h(sm + (kt & 1) * HSTAGE, acc, wm, wn, lane);
        if (kt + 2 < 8) {
            __syncthreads();
            ld_chunk_h(sm + (kt & 1) * HSTAGE, (kt + 2) * 64, tid, Ah, Al, Bh, Bl);
        }
    }

    #pragma unroll
    for (int mi = 0; mi < 4; mi++)
        #pragma unroll
        for (int h = 0; h < 2; h++) {
            int r = row0 + wm * 64 + mi * 16 + lr + h * 8;
            #pragma unroll
            for (int ni = 0; ni < 8; ni++) {
                int c = col0 + wn * 64 + ni * 8 + lq * 2;
                float x0 = acc[mi][ni][h * 2 + 0] + __ldg(&b1[c + 0]);
                float x1 = acc[mi][ni][h * 2 + 1] + __ldg(&b1[c + 1]);
                x0 = (x0 >= 0.f) ? x0 : NEG_SLOPE * x0;
                x1 = (x1 >= 0.f) ? x1 : NEG_SLOPE * x1;
                *(float2*)(g_H + (size_t)r * DIM + c) = make_float2(x0, x1);
                __nv_bfloat162 hb = __floats2bfloat162_rn(x0, x1);
                *(uint32_t*)(g_Hb + (size_t)r * DIM + c) = *(uint32_t*)&hb;
            }
        }
}

// ============================================================
// ||e_k||^2
// ============================================================
__global__ void esq_kernel(const float* __restrict__ E) {
    int row  = blockIdx.x * (blockDim.x >> 5) + (threadIdx.x >> 5);
    int lane = threadIdx.x & 31;
    const float* e = E + (size_t)row * DIM;
    float s = 0.f;
    for (int c = lane; c < DIM; c += 32) { float v = e[c]; s = fmaf(v, v, s); }
    #pragma unroll
    for (int o = 16; o; o >>= 1) s += __shfl_xor_sync(0xffffffffu, s, o);
    if (lane == 0) g_esq[row] = s;
}

// ============================================================
// fp32 refine: exact re-evaluation of top-2 candidates per row
// ============================================================
__device__ __forceinline__ float dot512(const float* __restrict__ a,
                                        const float* __restrict__ b, int lane)
{
    float s = 0.f;
    #pragma unroll
    for (int t = 0; t < 4; t++) {
        float4 x = *(const float4*)(a + (lane + 32 * t) * 4);
        float4 y = *(const float4*)(b + (lane + 32 * t) * 4);
        s = fmaf(x.x, y.x, s); s = fmaf(x.y, y.y, s);
        s = fmaf(x.z, y.z, s); s = fmaf(x.w, y.w, s);
    }
    #pragma unroll
    for (int o = 16; o; o >>= 1) s += __shfl_xor_sync(0xffffffffu, s, o);
    return s;
}

__global__ void __launch_bounds__(256)
refine_kernel(const float* __restrict__ Xmel, const float* __restrict__ E,
              const float* __restrict__ W2,  const float* __restrict__ b2)
{
    const int warp = threadIdx.x >> 5, lane = threadIdx.x & 31;
    const int row = blockIdx.x * 8 + warp;
    if (row >= BSZ) return;

    const float* xr = Xmel + (size_t)row * DIM;
    const float* hr = g_H  + (size_t)row * DIM;

    int mi1 = g_meli1[row], mi2 = g_meli2[row];
    float d1 = g_esq[mi1] - 2.f * dot512(xr, E + (size_t)mi1 * DIM, lane);
    float d2 = g_esq[mi2] - 2.f * dot512(xr, E + (size_t)mi2 * DIM, lane);
    int mel_idx = (d1 < d2 || (d1 == d2 && mi1 < mi2)) ? mi1 : mi2;

    int j1 = g_logi1[row], j2 = g_logi2[row];
    float l1 = dot512(hr, W2 + (size_t)j1 * DIM, lane) + b2[j1];
    float l2 = dot512(hr, W2 + (size_t)j2 * DIM, lane) + b2[j2];
    int eeg_idx = (l1 > l2 || (l1 == l2 && j1 < j2)) ? j1 : j2;

    float t = dot512(hr, W2 + (size_t)mel_idx * DIM, lane) + b2[mel_idx];

    if (lane == 0) {
        g_loss[row]  = g_lse[row] - t;
        g_match[row] = (eeg_idx == mel_idx) ? 1.f : 0.f;
    }
}

// ============================================================
// final mean reduction
// ============================================================
__global__ void reduce_kernel(float* __restrict__ out) {
    __shared__ float sl[1024];
    __shared__ float sa[1024];
    int tid = threadIdx.x;
    float a = 0.f, b = 0.f;
    for (int i = tid; i < BSZ; i += 1024) { a += g_loss[i]; b += g_match[i]; }
    sl[tid] = a; sa[tid] = b;
    __syncthreads();
    for (int o = 512; o; o >>= 1) {
        if (tid < o) { sl[tid] += sl[tid + o]; sa[tid] += sa[tid + o]; }
        __syncthreads();
    }
    if (tid == 0) {
        out[0] = sl[0] / (float)BSZ;
        out[1] = sa[0] / (float)BSZ;
    }
}

// ============================================================
extern "C" void kernel_launch(void* const* d_in, const int* in_sizes, int n_in,
                              void* d_out, int out_size)
{
    (void)in_sizes; (void)n_in; (void)out_size;
    const float* eeg = (const float*)d_in[0];
    const float* mel = (const float*)d_in[1];
    const float* emb = (const float*)d_in[2];
    const float* W1  = (const float*)d_in[3];
    const float* b1  = (const float*)d_in[4];
    const float* W2  = (const float*)d_in[5];
    const float* b2  = (const float*)d_in[6];
    float* out = (float*)d_out;

    cudaFuncSetAttribute(big_mma_all,  cudaFuncAttributeMaxDynamicSharedMemorySize, SMEM_BIG);
    cudaFuncSetAttribute(h_mma_kernel, cudaFuncAttributeMaxDynamicSharedMemorySize, SMEM_H);

    __nv_bfloat16 *dEb, *dW2b, *dXmb, *dXeh, *dXel, *dW1h, *dW1l;
    cudaGetSymbolAddress((void**)&dEb,  g_Eb);
    cudaGetSymbolAddress((void**)&dW2b, g_W2b);
    cudaGetSymbolAddress((void**)&dXmb, g_Xmb);
    cudaGetSymbolAddress((void**)&dXeh, g_Xeh);
    cudaGetSymbolAddress((void**)&dXel, g_Xel);
    cudaGetSymbolAddress((void**)&dW1h, g_W1h);
    cudaGetSymbolAddress((void**)&dW1l, g_W1l);

    esq_kernel<<<KNUM / 8, 256>>>(emb);
    conv_all<<<(N4_TOT + 255) / 256, 256>>>(
        (const float4*)emb, (const float4*)W2, (const float4*)mel,
        (const float4*)eeg, (const float4*)W1,
        (uint2*)dEb, (uint2*)dW2b, (uint2*)dXmb,
        (uint2*)dXeh, (uint2*)dXel, (uint2*)dW1h, (uint2*)dW1l);
    h_mma_kernel<<<dim3(BSZ / 128, DIM / 256), 256, SMEM_H>>>(b1);
    big_mma_all<<<256, 256, SMEM_BIG>>>(dXmb, dEb, dW2b, b2);
    refine_kernel<<<BSZ / 8, 256>>>(mel, emb, W2, b2);
    reduce_kernel<<<1, 1024>>>(out);
}

// round 15
// speedup vs baseline: 1.1914x; 1.0212x over previous
#include <cuda_runtime.h>
#include <cuda_bf16.h>
#include <math.h>
#include <stdint.h>

#define BSZ   16384
#define DIM   512
#define KNUM  8192
#define NEG_SLOPE 0.01f

// ---- scratch (static device globals) ----
__device__ float g_esq[KNUM];
__device__ float g_H[(size_t)BSZ * DIM];            // fp32 hidden (exact, for refine)
__device__ __nv_bfloat16 g_Hb[(size_t)BSZ * DIM];   // bf16 hidden (GEMM input)
__device__ __nv_bfloat16 g_Eb[(size_t)KNUM * DIM];  // bf16 embeddings
__device__ __nv_bfloat16 g_W2b[(size_t)KNUM * DIM]; // bf16 W2
__device__ __nv_bfloat16 g_Xmb[(size_t)BSZ * DIM];  // bf16 mel input
__device__ __nv_bfloat16 g_Xeh[(size_t)BSZ * DIM];  // eeg hi/lo split
__device__ __nv_bfloat16 g_Xel[(size_t)BSZ * DIM];
__device__ __nv_bfloat16 g_W1h[(size_t)DIM * DIM];  // W1 hi/lo split
__device__ __nv_bfloat16 g_W1l[(size_t)DIM * DIM];
__device__ int   g_meli1[BSZ], g_meli2[BSZ];
__device__ int   g_logi1[BSZ], g_logi2[BSZ];
__device__ float g_lse[BSZ];
__device__ float g_loss[BSZ], g_match[BSZ];

// ============================================================
// common PTX helpers
// ============================================================
__device__ __forceinline__ uint32_t smem_u32(const void* p) {
    uint32_t a;
    asm("{ .reg .u64 t; cvta.to.shared.u64 t, %1; cvt.u32.u64 %0, t; }" : "=r"(a) : "l"(p));
    return a;
}
__device__ __forceinline__ void ldsm4(uint32_t& r0, uint32_t& r1, uint32_t& r2, uint32_t& r3,
                                      uint32_t addr) {
    asm volatile("ldmatrix.sync.aligned.m8n8.x4.shared.b16 {%0,%1,%2,%3}, [%4];"
                 : "=r"(r0), "=r"(r1), "=r"(r2), "=r"(r3) : "r"(addr));
}
__device__ __forceinline__ void cp16(void* dst, const void* src) {
    unsigned d = smem_u32(dst);
    asm volatile("cp.async.cg.shared.global [%0], [%1], 16;" :: "r"(d), "l"(src));
}
#define CP_COMMIT() asm volatile("cp.async.commit_group;" ::: "memory")

// bf16 m16n8k16
__device__ __forceinline__ void mma_bf16(float* d, const uint32_t* a, const uint32_t* b) {
    asm volatile(
        "mma.sync.aligned.m16n8k16.row.col.f32.bf16.bf16.f32 "
        "{%0,%1,%2,%3},{%4,%5,%6,%7},{%8,%9},{%0,%1,%2,%3};"
        : "+f"(d[0]), "+f"(d[1]), "+f"(d[2]), "+f"(d[3])
        : "r"(a[0]), "r"(a[1]), "r"(a[2]), "r"(a[3]), "r"(b[0]), "r"(b[1]));
}

// ============================================================
// big-GEMM (bf16): CTA tile 128(M) x 128(N-pass), k-chunk 64, 8 warps (4x2),
// warp tile 32x64, 3-stage cp.async ring, CONTINUOUS across all 64 N-passes
// (ring never drains; epilogue overlaps next-pass loads). 2 CTAs/SM.
// ============================================================
#define MROWS   128
#define NCOLS   128
#define BROWB   144
#define BSTAGE  ((MROWS + NCOLS) * BROWB)   // 36864 B
#define SMEM_BIG (3 * BSTAGE)               // 110592 B -> 2 CTAs/SM
#define NCHUNK  512                         // 64 passes x 8 k-chunks

// chunk loader for global chunk index g: A[128][64] (kb = (g&7)*64) +
// B rows (g>>3)*128 .. +127, same kb.
__device__ __forceinline__ void ld_chunk_g(char* sbase,
                                           const __nv_bfloat16* Ag,
                                           const __nv_bfloat16* B,
                                           int g, int tid)
{
    const int nt = g >> 3;
    const int kb = (g & 7) * 64;
    const __nv_bfloat16* Bg = B + (size_t)nt * NCOLS * DIM;
    #pragma unroll
    for (int i = 0; i < 4; i++) {
        int f = tid + (i << 8);           // 0..1023
        int r = f >> 3, c = f & 7;        // A row 0..127
        cp16(sbase + r * BROWB + c * 16, Ag + (size_t)r * DIM + kb + c * 8);
    }
    #pragma unroll
    for (int i = 0; i < 4; i++) {
        int f = tid + (i << 8);
        int r = f >> 3, c = f & 7;        // B row 0..127
        cp16(sbase + (128 + r) * BROWB + c * 16, Bg + (size_t)r * DIM + kb + c * 8);
    }
    CP_COMMIT();
}

// 8-warp compute (4x2): warp tile 32x64, acc[2][8][4]
__device__ __forceinline__ void compute_stage_bf(const char* sbuf, float acc[2][8][4],
                                                 int wm, int wn, int lane)
{
    const uint32_t sb = smem_u32(sbuf);
    const uint32_t aAddr = sb + (uint32_t)((wm * 32 + (lane & 7) + ((lane >> 3) & 1) * 8) * BROWB
                                           + ((lane >> 4) & 1) * 16);
    const uint32_t bAddr = sb + (uint32_t)((128 + wn * 64 + (lane & 7) + ((lane >> 4) & 1) * 8) * BROWB
                                           + ((lane >> 3) & 1) * 16);
    #pragma unroll
    for (int k16 = 0; k16 < 4; k16++) {
        const uint32_t kb = (uint32_t)k16 * 32u;
        uint32_t a[2][4], b[8][2];
        #pragma unroll
        for (int mi = 0; mi < 2; mi++)
            ldsm4(a[mi][0], a[mi][1], a[mi][2], a[mi][3],
                  aAddr + (uint32_t)mi * (16 * BROWB) + kb);
        #pragma unroll
        for (int p = 0; p < 4; p++)
            ldsm4(b[2 * p][0], b[2 * p][1], b[2 * p + 1][0], b[2 * p + 1][1],
                  bAddr + (uint32_t)p * (16 * BROWB) + kb);
        #pragma unroll
        for (int mi = 0; mi < 2; mi++)
            #pragma unroll
            for (int ni = 0; ni < 8; ni++)
                mma_bf16(acc[mi][ni], a[mi], b[ni]);
    }
}

// top-2 insertion with index tiebreak + dedupe
__device__ __forceinline__ void ins_min(float v, int i, float& v1, int& i1, float& v2, int& i2) {
    if (v < v1 || (v == v1 && i < i1)) {
        if (i != i1) { v2 = v1; i2 = i1; }
        v1 = v; i1 = i;
    } else if (i != i1 && (v < v2 || (v == v2 && i < i2))) { v2 = v; i2 = i; }
}
__device__ __forceinline__ void ins_max(float v, int i, float& v1, int& i1, float& v2, int& i2) {
    if (v > v1 || (v == v1 && i < i1)) {
        if (i != i1) { v2 = v1; i2 = i1; }
        v1 = v; i1 = i;
    } else if (i != i1 && (v > v2 || (v == v2 && i < i2))) { v2 = v; i2 = i; }
}

// ============================================================
// MERGED big fused kernel: grid 256, 2 CTAs/SM, continuous pipeline.
// bx<128 -> mel argmin block bx; bx>=128 -> logits block bx-128 (reads g_Hb).
// Logits epilogue: max-free sum-exp (logits bounded |x|<~2 -> fp32-safe).
// ============================================================
__global__ void __launch_bounds__(256, 2)
big_mma_all(const __nv_bfloat16* __restrict__ Amel,
            const __nv_bfloat16* __restrict__ Bmel,
            const __nv_bfloat16* __restrict__ Blog,
            const float* __restrict__ b2)
{
    extern __shared__ float smf[];
    char* sm = (char*)smf;
    const int tid = threadIdx.x, w = tid >> 5, lane = tid & 31;
    const int wm = w >> 1, wn = w & 1, lr = lane >> 2, lq = lane & 3;
    const bool LOGITS = (blockIdx.x >= 128);
    const int row0 = (blockIdx.x & 127) * MROWS;
    const __nv_bfloat16* A = LOGITS ? (const __nv_bfloat16*)g_Hb : Amel;
    const __nv_bfloat16* B = LOGITS ? Blog : Bmel;
    const __nv_bfloat16* Ag = A + (size_t)row0 * DIM;

    float v1[4], v2[4], s[4]; int i1[4], i2[4];
    #pragma unroll
    for (int st = 0; st < 4; st++) {
        v1[st] = LOGITS ? -INFINITY : INFINITY; v2[st] = v1[st];
        i1[st] = 0x7fffffff; i2[st] = 0x7fffffff;
        s[st] = 0.f;
    }

    float acc[2][8][4];
    ld_chunk_g(sm + 0 * BSTAGE, Ag, B, 0, tid);
    ld_chunk_g(sm + 1 * BSTAGE, Ag, B, 1, tid);

    for (int g = 0; g < NCHUNK; g++) {
        const int kt = g & 7;
        if (kt == 0) {
            #pragma unroll
            for (int mi = 0; mi < 2; mi++)
                #pragma unroll
                for (int ni = 0; ni < 8; ni++)
                    #pragma unroll
                    for (int j = 0; j < 4; j++) acc[mi][ni][j] = 0.f;
        }
        if (g < NCHUNK - 2) asm volatile("cp.async.wait_group 1;" ::: "memory");
        else                asm volatile("cp.async.wait_group 0;" ::: "memory");
        __syncthreads();
        compute_stage_bf(sm + (g % 3) * BSTAGE, acc, wm, wn, lane);
        if (g + 2 < NCHUNK)
            ld_chunk_g(sm + ((g + 2) % 3) * BSTAGE, Ag, B, g + 2, tid);

        if (kt == 7) {
            const int nt = g >> 3;
            #pragma unroll
            for (int mi = 0; mi < 2; mi++)
                #pragma unroll
                for (int h = 0; h < 2; h++) {
                    const int st = mi * 2 + h;
                    if (LOGITS) {
                        float ssum = 0.f;
                        #pragma unroll
                        for (int ni = 0; ni < 8; ni++)
                            #pragma unroll
                            for (int cc = 0; cc < 2; cc++) {
                                int col = nt * NCOLS + wn * 64 + ni * 8 + lq * 2 + cc;
                                float x = acc[mi][ni][h * 2 + cc] + __ldg(&b2[col]);
                                ssum += __expf(x);   // bounded logits: no overflow risk
                                if (x > v1[st]) { v2[st] = v1[st]; i2[st] = i1[st]; v1[st] = x; i1[st] = col; }
                                else if (x > v2[st]) { v2[st] = x; i2[st] = col; }
                            }
                        s[st] += ssum;
                    } else {
                        #pragma unroll
                        for (int ni = 0; ni < 8; ni++)
                            #pragma unroll
                            for (int cc = 0; cc < 2; cc++) {
                                int col = nt * NCOLS + wn * 64 + ni * 8 + lq * 2 + cc;
                                float d = fmaf(-2.f, acc[mi][ni][h * 2 + cc], __ldg(&g_esq[col]));
                                if (d < v1[st]) { v2[st] = v1[st]; i2[st] = i1[st]; v1[st] = d; i1[st] = col; }
                                else if (d < v2[st]) { v2[st] = d; i2[st] = col; }
                            }
                    }
                }
        }
    }

    // merge: 8 slots per row (wn x lq), rows 0..127
    __syncthreads();
    float* v1s = smf;                  float* v2s = smf + 1024;
    int*   i1s = (int*)(smf + 2048);   int*   i2s = (int*)(smf + 3072);
    float* ss  = smf + 4096;
    const int slot = wn * 4 + lq;
    #pragma unroll
    for (int mi = 0; mi < 2; mi++)
        #pragma unroll
        for (int h = 0; h < 2; h++) {
            int r  = wm * 32 + mi * 16 + lr + h * 8;
            int st = mi * 2 + h;
            v1s[r * 8 + slot] = v1[st]; v2s[r * 8 + slot] = v2[st];
            i1s[r * 8 + slot] = i1[st]; i2s[r * 8 + slot] = i2[st];
            if (LOGITS) ss[r * 8 + slot] = s[st];
        }
    __syncthreads();
    if (tid < 128) {
        const int grow = row0 + tid;
        if (LOGITS) {
            float bv1 = -INFINITY, bv2 = -INFINITY; int bi1 = 0x7fffffff, bi2 = 0x7fffffff;
            float S = 0.f;
            #pragma unroll
            for (int k = 0; k < 8; k++) {
                ins_max(v1s[tid * 8 + k], i1s[tid * 8 + k], bv1, bi1, bv2, bi2);
                ins_max(v2s[tid * 8 + k], i2s[tid * 8 + k], bv1, bi1, bv2, bi2);
                S += ss[tid * 8 + k];
            }
            g_logi1[grow] = bi1; g_logi2[grow] = bi2;
            g_lse[grow]   = logf(S);
        } else {
            float bv1 = INFINITY, bv2 = INFINITY; int bi1 = 0x7fffffff, bi2 = 0x7fffffff;
            #pragma unroll
            for (int k = 0; k < 8; k++) {
                ins_min(v1s[tid * 8 + k], i1s[tid * 8 + k], bv1, bi1, bv2, bi2);
                ins_min(v2s[tid * 8 + k], i2s[tid * 8 + k], bv1, bi1, bv2, bi2);
            }
            g_meli1[grow] = bi1; g_meli2[grow] = bi2;
        }
    }
}

// ============================================================
// fused cast kernel: emb->bf16, W2->bf16, mel->bf16, eeg->split, W1->split
// ============================================================
#define N4_EMB  (KNUM * DIM / 4)
#define N4_W2   (KNUM * DIM / 4)
#define N4_MEL  (BSZ * DIM / 4)
#define N4_EEG  (BSZ * DIM / 4)
#define N4_W1   (DIM * DIM / 4)
#define N4_TOT  (N4_EMB + N4_W2 + N4_MEL + N4_EEG + N4_W1)

__device__ __forceinline__ uint2 pack_bf16(float4 v) {
    __nv_bfloat162 a = __floats2bfloat162_rn(v.x, v.y);
    __nv_bfloat162 b = __floats2bfloat162_rn(v.z, v.w);
    uint2 u; u.x = *(uint32_t*)&a; u.y = *(uint32_t*)&b;
    return u;
}

__global__ void conv_all(const float4* __restrict__ emb, const float4* __restrict__ W2,
                         const float4* __restrict__ mel, const float4* __restrict__ eeg,
                         const float4* __restrict__ W1,
                         uint2* __restrict__ oE, uint2* __restrict__ oW2,
                         uint2* __restrict__ oM,
                         uint2* __restrict__ oXh, uint2* __restrict__ oXl,
                         uint2* __restrict__ oWh, uint2* __restrict__ oWl)
{
    int i = blockIdx.x * blockDim.x + threadIdx.x;
    if (i >= N4_TOT) return;
    if (i < N4_EMB) {
        oE[i] = pack_bf16(emb[i]);
    } else if (i < N4_EMB + N4_W2) {
        int j = i - N4_EMB;
        oW2[j] = pack_bf16(W2[j]);
    } else if (i < N4_EMB + N4_W2 + N4_MEL) {
        int j = i - N4_EMB - N4_W2;
        oM[j] = pack_bf16(mel[j]);
    } else if (i < N4_EMB + N4_W2 + N4_MEL + N4_EEG) {
        int j = i - N4_EMB - N4_W2 - N4_MEL;
        float4 v = eeg[j];
        __nv_bfloat16 hx = __float2bfloat16_rn(v.x), hy = __float2bfloat16_rn(v.y);
        __nv_bfloat16 hz = __float2bfloat16_rn(v.z), hw = __float2bfloat16_rn(v.w);
        __nv_bfloat162 ha; ha.x = hx; ha.y = hy;
        __nv_bfloat162 hb; hb.x = hz; hb.y = hw;
        __nv_bfloat162 la = __floats2bfloat162_rn(v.x - __bfloat162float(hx), v.y - __bfloat162float(hy));
        __nv_bfloat162 lb = __floats2bfloat162_rn(v.z - __bfloat162float(hz), v.w - __bfloat162float(hw));
        uint2 uh; uh.x = *(uint32_t*)&ha; uh.y = *(uint32_t*)&hb;
        uint2 ul; ul.x = *(uint32_t*)&la; ul.y = *(uint32_t*)&lb;
        oXh[j] = uh; oXl[j] = ul;
    } else {
        int j = i - N4_EMB - N4_W2 - N4_MEL - N4_EEG;
        float4 v = W1[j];
        __nv_bfloat16 hx = __float2bfloat16_rn(v.x), hy = __float2bfloat16_rn(v.y);
        __nv_bfloat16 hz = __float2bfloat16_rn(v.z), hw = __float2bfloat16_rn(v.w);
        __nv_bfloat162 ha; ha.x = hx; ha.y = hy;
        __nv_bfloat162 hb; hb.x = hz; hb.y = hw;
        __nv_bfloat162 la = __floats2bfloat162_rn(v.x - __bfloat162float(hx), v.y - __bfloat162float(hy));
        __nv_bfloat162 lb = __floats2bfloat162_rn(v.z - __bfloat162float(hz), v.w - __bfloat162float(hw));
        uint2 uh; uh.x = *(uint32_t*)&ha; uh.y = *(uint32_t*)&hb;
        uint2 ul; ul.x = *(uint32_t*)&la; ul.y = *(uint32_t*)&lb;
        oWh[j] = uh; oWl[j] = ul;
    }
}

// ============================================================
// h kernel: H = leakyrelu(X*W1^T + b1) via 3x bf16-split
// (Ah*Bh + Ah*Bl + Al*Bh, fp32 accum). CTA 128x256, k-chunk 64, 2-stage ring.
// ============================================================
#define H_AL   (128 * BROWB)
#define H_BH   (2 * 128 * BROWB)
#define H_BL   (H_BH + 256 * BROWB)
#define HSTAGE (H_BL + 256 * BROWB)     // 110592
#define SMEM_H (2 * HSTAGE)             // 221184

__device__ __forceinline__ void ld_chunk_h(char* sbase, int kb, int tid,
                                           const __nv_bfloat16* Ah, const __nv_bfloat16* Al,
                                           const __nv_bfloat16* Bh, const __nv_bfloat16* Bl)
{
    #pragma unroll
    for (int i = 0; i < 4; i++) {
        int f = tid + (i << 8);
        int r = f >> 3, c = f & 7;
        cp16(sbase +        r * BROWB + c * 16, Ah + (size_t)r * DIM + kb + c * 8);
        cp16(sbase + H_AL + r * BROWB + c * 16, Al + (size_t)r * DIM + kb + c * 8);
    }
    #pragma unroll
    for (int i = 0; i < 8; i++) {
        int f = tid + (i << 8);
        int r = f >> 3, c = f & 7;
        cp16(sbase + H_BH + r * BROWB + c * 16, Bh + (size_t)r * DIM + kb + c * 8);
        cp16(sbase + H_BL + r * BROWB + c * 16, Bl + (size_t)r * DIM + kb + c * 8);
    }
    CP_COMMIT();
}

__device__ __forceinline__ void compute_stage_h(const char* sbuf, float acc[4][8][4],
                                                int wm, int wn, int lane)
{
    const uint32_t sb = smem_u32(sbuf);
    const uint32_t aoff = (uint32_t)((wm * 64 + (lane & 7) + ((lane >> 3) & 1) * 8) * BROWB
                                     + ((lane >> 4) & 1) * 16);
    const uint32_t boff = (uint32_t)((wn * 64 + (lane & 7) + ((lane >> 4) & 1) * 8) * BROWB
                                     + ((lane >> 3) & 1) * 16);
    const uint32_t aH = sb + aoff, aL = sb + H_AL + aoff;
    const uint32_t bH = sb + H_BH + boff, bL = sb + H_BL + boff;
    #pragma unroll
    for (int k16 = 0; k16 < 4; k16++) {
        const uint32_t kb = (uint32_t)k16 * 32u;
        uint32_t ah[4][4], al[4][4], bh[8][2], bl[8][2];
        #pragma unroll
        for (int mi = 0; mi < 4; mi++) {
            ldsm4(ah[mi][0], ah[mi][1], ah[mi][2], ah[mi][3], aH + (uint32_t)mi * (16 * BROWB) + kb);
            ldsm4(al[mi][0], al[mi][1], al[mi][2], al[mi][3], aL + (uint32_t)mi * (16 * BROWB) + kb);
        }
        #pragma unroll
        for (int p = 0; p < 4; p++) {
            ldsm4(bh[2*p][0], bh[2*p][1], bh[2*p+1][0], bh[2*p+1][1], bH + (uint32_t)p * (16 * BROWB) + kb);
            ldsm4(bl[2*p][0], bl[2*p][1], bl[2*p+1][0], bl[2*p+1][1], bL + (uint32_t)p * (16 * BROWB) + kb);
        }
        #pragma unroll
        for (int mi = 0; mi < 4; mi++)
            #pragma unroll
            for (int ni = 0; ni < 8; ni++) {
                mma_bf16(acc[mi][ni], ah[mi], bh[ni]);
                mma_bf16(acc[mi][ni], ah[mi], bl[ni]);
                mma_bf16(acc[mi][ni], al[mi], bh[ni]);
            }
    }
}

__global__ void __launch_bounds__(256, 1)
h_mma_kernel(const float* __restrict__ b1)
{
    extern __shared__ float smf[];
    char* sm = (char*)smf;
    const int tid = threadIdx.x, w = tid >> 5, lane = tid & 31;
    const int wm = w >> 2, wn = w & 3, lr = lane >> 2, lq = lane & 3;
    const int row0 = blockIdx.x * 128;
    const int col0 = blockIdx.y * 256;
    const __nv_bfloat16* Ah = g_Xeh + (size_t)row0 * DIM;
    const __nv_bfloat16* Al = g_Xel + (size_t)row0 * DIM;
    const __nv_bfloat16* Bh = g_W1h + (size_t)col0 * DIM;
    const __nv_bfloat16* Bl = g_W1l + (size_t)col0 * DIM;

    float acc[4][8][4];
    #pragma unroll
    for (int mi = 0; mi < 4; mi++)
        #pragma unroll
        for (int ni = 0; ni < 8; ni++)
            #pragma unroll
            for (int j = 0; j < 4; j++) acc[mi][ni][j] = 0.f;

    ld_chunk_h(sm + 0 * HSTAGE, 0,  tid, Ah, Al, Bh, Bl);
    ld_chunk_h(sm + 1 * HSTAGE, 64, tid, Ah, Al, Bh, Bl);

    for (int kt = 0; kt < 8; kt++) {
        if (kt < 7) asm volatile("cp.async.wait_group 1;" ::: "memory");
        else        asm volatile("cp.async.wait_group 0;" ::: "memory");
        __syncthreads();
        compute_stage_h(sm + (kt & 1) * HSTAGE, acc, wm, wn, lane);
        if (kt + 2 < 8) {
            __syncthreads();
            ld_chunk_h(sm + (kt & 1) * HSTAGE, (kt + 2) * 64, tid, Ah, Al, Bh, Bl);
        }
    }

    #pragma unroll
    for (int mi = 0; mi < 4; mi++)
        #pragma unroll
        for (int h = 0; h < 2; h++) {
            int r = row0 + wm * 64 + mi * 16 + lr + h * 8;
            #pragma unroll
            for (int ni = 0; ni < 8; ni++) {
                int c = col0 + wn * 64 + ni * 8 + lq * 2;
                float x0 = acc[mi][ni][h * 2 + 0] + __ldg(&b1[c + 0]);
                float x1 = acc[mi][ni][h * 2 + 1] + __ldg(&b1[c + 1]);
                x0 = (x0 >= 0.f) ? x0 : NEG_SLOPE * x0;
                x1 = (x1 >= 0.f) ? x1 : NEG_SLOPE * x1;
                *(float2*)(g_H + (size_t)r * DIM + c) = make_float2(x0, x1);
                __nv_bfloat162 hb = __floats2bfloat162_rn(x0, x1);
                *(uint32_t*)(g_Hb + (size_t)r * DIM + c) = *(uint32_t*)&hb;
            }
        }
}

// ============================================================
// ||e_k||^2
// ============================================================
__global__ void esq_kernel(const float* __restrict__ E) {
    int row  = blockIdx.x * (blockDim.x >> 5) + (threadIdx.x >> 5);
    int lane = threadIdx.x & 31;
    const float* e = E + (size_t)row * DIM;
    float s = 0.f;
    for (int c = lane; c < DIM; c += 32) { float v = e[c]; s = fmaf(v, v, s); }
    #pragma unroll
    for (int o = 16; o; o >>= 1) s += __shfl_xor_sync(0xffffffffu, s, o);
    if (lane == 0) g_esq[row] = s;
}

// ============================================================
// fp32 refine: exact re-evaluation of top-2 candidates per row
// ============================================================
__device__ __forceinline__ float dot512(const float* __restrict__ a,
                                        const float* __restrict__ b, int lane)
{
    float s = 0.f;
    #pragma unroll
    for (int t = 0; t < 4; t++) {
        float4 x = *(const float4*)(a + (lane + 32 * t) * 4);
        float4 y = *(const float4*)(b + (lane + 32 * t) * 4);
        s = fmaf(x.x, y.x, s); s = fmaf(x.y, y.y, s);
        s = fmaf(x.z, y.z, s); s = fmaf(x.w, y.w, s);
    }
    #pragma unroll
    for (int o = 16; o; o >>= 1) s += __shfl_xor_sync(0xffffffffu, s, o);
    return s;
}

__global__ void __launch_bounds__(256)
refine_kernel(const float* __restrict__ Xmel, const float* __restrict__ E,
              const float* __restrict__ W2,  const float* __restrict__ b2)
{
    const int warp = threadIdx.x >> 5, lane = threadIdx.x & 31;
    const int row = blockIdx.x * 8 + warp;
    if (row >= BSZ) return;

    const float* xr = Xmel + (size_t)row * DIM;
    const float* hr = g_H  + (size_t)row * DIM;

    int mi1 = g_meli1[row], mi2 = g_meli2[row];
    float d1 = g_esq[mi1] - 2.f * dot512(xr, E + (size_t)mi1 * DIM, lane);
    float d2 = g_esq[mi2] - 2.f * dot512(xr, E + (size_t)mi2 * DIM, lane);
    int mel_idx = (d1 < d2 || (d1 == d2 && mi1 < mi2)) ? mi1 : mi2;

    int j1 = g_logi1[row], j2 = g_logi2[row];
    float l1 = dot512(hr, W2 + (size_t)j1 * DIM, lane) + b2[j1];
    float l2 = dot512(hr, W2 + (size_t)j2 * DIM, lane) + b2[j2];
    int eeg_idx = (l1 > l2 || (l1 == l2 && j1 < j2)) ? j1 : j2;

    float t = dot512(hr, W2 + (size_t)mel_idx * DIM, lane) + b2[mel_idx];

    if (lane == 0) {
        g_loss[row]  = g_lse[row] - t;
        g_match[row] = (eeg_idx == mel_idx) ? 1.f : 0.f;
    }
}

// ============================================================
// final mean reduction
// ============================================================
__global__ void reduce_kernel(float* __restrict__ out) {
    __shared__ float sl[1024];
    __shared__ float sa[1024];
    int tid = threadIdx.x;
    float a = 0.f, b = 0.f;
    for (int i = tid; i < BSZ; i += 1024) { a += g_loss[i]; b += g_match[i]; }
    sl[tid] = a; sa[tid] = b;
    __syncthreads();
    for (int o = 512; o; o >>= 1) {
        if (tid < o) { sl[tid] += sl[tid + o]; sa[tid] += sa[tid + o]; }
        __syncthreads();
    }
    if (tid == 0) {
        out[0] = sl[0] / (float)BSZ;
        out[1] = sa[0] / (float)BSZ;
    }
}

// ============================================================
extern "C" void kernel_launch(void* const* d_in, const int* in_sizes, int n_in,
                              void* d_out, int out_size)
{
    (void)in_sizes; (void)n_in; (void)out_size;
    const float* eeg = (const float*)d_in[0];
    const float* mel = (const float*)d_in[1];
    const float* emb = (const float*)d_in[2];
    const float* W1  = (const float*)d_in[3];
    const float* b1  = (const float*)d_in[4];
    const float* W2  = (const float*)d_in[5];
    const float* b2  = (const float*)d_in[6];
    float* out = (float*)d_out;

    cudaFuncSetAttribute(big_mma_all,  cudaFuncAttributeMaxDynamicSharedMemorySize, SMEM_BIG);
    cudaFuncSetAttribute(h_mma_kernel, cudaFuncAttributeMaxDynamicSharedMemorySize, SMEM_H);

    __nv_bfloat16 *dEb, *dW2b, *dXmb, *dXeh, *dXel, *dW1h, *dW1l;
    cudaGetSymbolAddress((void**)&dEb,  g_Eb);
    cudaGetSymbolAddress((void**)&dW2b, g_W2b);
    cudaGetSymbolAddress((void**)&dXmb, g_Xmb);
    cudaGetSymbolAddress((void**)&dXeh, g_Xeh);
    cudaGetSymbolAddress((void**)&dXel, g_Xel);
    cudaGetSymbolAddress((void**)&dW1h, g_W1h);
    cudaGetSymbolAddress((void**)&dW1l, g_W1l);

    esq_kernel<<<KNUM / 8, 256>>>(emb);
    conv_all<<<(N4_TOT + 255) / 256, 256>>>(
        (const float4*)emb, (const float4*)W2, (const float4*)mel,
        (const float4*)eeg, (const float4*)W1,
        (uint2*)dEb, (uint2*)dW2b, (uint2*)dXmb,
        (uint2*)dXeh, (uint2*)dXel, (uint2*)dW1h, (uint2*)dW1l);
    h_mma_kernel<<<dim3(BSZ / 128, DIM / 256), 256, SMEM_H>>>(b1);
    big_mma_all<<<256, 256, SMEM_BIG>>>(dXmb, dEb, dW2b, b2);
    refine_kernel<<<BSZ / 8, 256>>>(mel, emb, W2, b2);
    reduce_kernel<<<1, 1024>>>(out);
}